// round 8
// baseline (speedup 1.0000x reference)
#include <cuda_runtime.h>
#include <math.h>

// Problem dims (fixed by the dataset)
#define Q   512
#define D   131072           // 512*16*16
#define D4  (D/4)            // 32768 float4
#define B   2
#define A   16
#define C   19
#define HW  65536            // 256*256
#define REFINE_CONF 0.968f

// k_dots tiling: 8 rows/block, register-held tgt
#define CH     2048          // float4 per D-chunk
#define S_DOTS (D4/CH)       // 16 D-splits
#define RPB    8             // queue rows per block
#define ROWG   (Q/RPB)       // 64 row-groups
#define NDOT   (S_DOTS*ROWG) // 1024 dot blocks
#define CONFB  512           // confidence blocks: 256 pixels each (2/thread)
#define NTT    32            // tt blocks
// k_d2 tiling
#define S_TT   16
#define CHTT   (D4/S_TT)     // 2048 float4
#define S_D2   32
#define CH2    (D4/S_D2)     // 1024 float4

// ---------------- scratch (no allocations allowed) ----------------
__device__ float g_pqq[S_DOTS][Q];        // partial ||queue_q||^2
__device__ float g_pqt[S_DOTS][Q][B];     // partial queue_q . tgt_b
__device__ float g_ptt[S_TT][B];          // partial ||tgt_b||^2
__device__ int   g_imin[B];
__device__ float g_cd2[B];                // closest distance^2
__device__ float g_pd2[S_D2][B][A];       // partial ||aug - closest||^2
__device__ int   g_selidx[B][16];
__device__ int   g_selcnt[B];
__device__ int   g_mcnt[B];
__device__ unsigned char g_pmask[B * HW]; // low-confidence mask

__device__ __forceinline__ float dot4(float4 a, float4 b, float acc) {
    return fmaf(a.x, b.x, fmaf(a.y, b.y, fmaf(a.z, b.z, fmaf(a.w, b.w, acc))));
}

// ---------------- kernel 1: conf mask + queue dots + tt (one grid) ----------------
__global__ __launch_bounds__(128) void k_dots_tt(const float* __restrict__ queue,
                                                 const float* __restrict__ tgt,
                                                 const float* __restrict__ tgt_logits) {
    const int bid = blockIdx.x;
    const int tid = threadIdx.x;
    const int lane = tid & 31, warp = tid >> 5;
    __shared__ float red[RPB * 3][128];           // 12 KB reduce buffer

    if (bid < CONFB) {
        // confidence blocks: 19 INDEPENDENT loads (MLP), then reduce.
#pragma unroll
        for (int u = 0; u < 2; u++) {
            const int pix = bid * 256 + u * 128 + tid;
            const int b = pix >> 16;
            const int p = pix & (HW - 1);
            const float* __restrict__ tp = tgt_logits + (size_t)b * C * HW + p;
            float tl[C];
#pragma unroll
            for (int c = 0; c < C; c++) tl[c] = tp[(size_t)c * HW];
            float mx = tl[0];
#pragma unroll
            for (int c = 1; c < C; c++) mx = fmaxf(mx, tl[c]);
            float s = 0.f;
#pragma unroll
            for (int c = 0; c < C; c++) s += __expf(tl[c] - mx);
            g_pmask[pix] = ((1.0f / s) < REFINE_CONF) ? 1 : 0;
        }
    } else if (bid < CONFB + NDOT) {
        const int db   = bid - CONFB;
        const int s    = db >> 6;                 // D-split (ROWG = 64)
        const int rowg = db & 63;
        const int q0   = rowg * RPB;
        const int i0   = s * CH;
        const float4* __restrict__ qf = (const float4*)queue;
        const float4* __restrict__ tf = (const float4*)tgt;

        float acc[RPB * 3];
#pragma unroll
        for (int v = 0; v < RPB * 3; v++) acc[v] = 0.f;

        const float4* __restrict__ qbase = qf + (size_t)q0 * D4 + i0 + tid;
        const float4* __restrict__ tbase = tf + i0 + tid;

        for (int off = 0; off < CH; off += 128) {
            // 10 front-batched independent loads: 2 tgt (L2-hot) + 8 queue rows (DRAM)
            float4 t0 = tbase[off];
            float4 t1 = tbase[D4 + off];
            float4 qv[RPB];
#pragma unroll
            for (int r = 0; r < RPB; r++) qv[r] = qbase[(size_t)r * D4 + off];
#pragma unroll
            for (int r = 0; r < RPB; r++) {
                acc[r * 3 + 0] = dot4(qv[r], qv[r], acc[r * 3 + 0]);
                acc[r * 3 + 1] = dot4(qv[r], t0,    acc[r * 3 + 1]);
                acc[r * 3 + 2] = dot4(qv[r], t1,    acc[r * 3 + 2]);
            }
        }

        // single block reduction at the end
#pragma unroll
        for (int v = 0; v < RPB * 3; v++) red[v][tid] = acc[v];
        __syncthreads();
        // 4 warps x 6 values each
#pragma unroll
        for (int c = 0; c < 6; c++) {
            const int v = warp * 6 + c;           // 0..23
            float ssum = red[v][lane] + red[v][lane + 32] + red[v][lane + 64] + red[v][lane + 96];
#pragma unroll
            for (int o = 16; o > 0; o >>= 1) ssum += __shfl_down_sync(0xFFFFFFFFu, ssum, o);
            if (lane == 0) {
                const int r = v / 3, cc = v % 3;
                if (cc == 0) g_pqq[s][q0 + r]         = ssum;
                else         g_pqt[s][q0 + r][cc - 1] = ssum;
            }
        }
    } else {
        // tt blocks: 32 of them, (sc, b)
        const int s2 = bid - CONFB - NDOT;
        const int b  = s2 & 1;
        const int sc = s2 >> 1;                   // 0..15
        const float4* __restrict__ tf = (const float4*)tgt + (size_t)b * D4 + sc * CHTT;
        float sum = 0.f;
        for (int i = tid; i < CHTT; i += 128) {
            float4 t = tf[i];
            sum = dot4(t, t, sum);
        }
#pragma unroll
        for (int o = 16; o > 0; o >>= 1) sum += __shfl_down_sync(0xFFFFFFFFu, sum, o);
        if (lane == 0) red[0][warp] = sum;
        __syncthreads();
        if (tid < 4) {
            sum = red[0][tid];
#pragma unroll
            for (int o = 2; o > 0; o >>= 1) sum += __shfl_down_sync(0xFu, sum, o);
            if (tid == 0) g_ptt[sc][b] = sum;
        }
    }
}

// ---------------- kernel 2: reduce partials + argmin (stable, first idx on tie) ----------------
__global__ __launch_bounds__(512) void k_reduce_argmin() {
    const int tid = threadIdx.x;   // == q, Q == 512
    float qq = 0.f, qt0 = 0.f, qt1 = 0.f;
#pragma unroll
    for (int s = 0; s < S_DOTS; s++) {
        qq  += g_pqq[s][tid];
        qt0 += g_pqt[s][tid][0];
        qt1 += g_pqt[s][tid][1];
    }
    __shared__ float tts[B];
    if (tid < B) {
        float t = 0.f;
#pragma unroll
        for (int s = 0; s < S_TT; s++) t += g_ptt[s][tid];
        tts[tid] = t;
    }
    __shared__ float sval[512];
    __shared__ int   sidx[512];
    __syncthreads();
    for (int b = 0; b < B; b++) {
        float qt = (b == 0) ? qt0 : qt1;
        float v = qq - 2.0f * qt + tts[b];
        sval[tid] = v; sidx[tid] = tid;
        __syncthreads();
        for (int s = 256; s > 0; s >>= 1) {
            if (tid < s) {
                float ov = sval[tid + s]; int oi = sidx[tid + s];
                if (ov < sval[tid] || (ov == sval[tid] && oi < sidx[tid])) {
                    sval[tid] = ov; sidx[tid] = oi;
                }
            }
            __syncthreads();
        }
        if (tid == 0) { g_imin[b] = sidx[0]; g_cd2[b] = sval[0]; }
        __syncthreads();
    }
}

// ---------------- kernel 3: ||aug[b,a] - closest_b||^2, one pass, MLP 8 ----------------
__global__ __launch_bounds__(256) void k_d2(const float* __restrict__ auged,
                                            const float* __restrict__ queue) {
    const int pair = blockIdx.x & 31;            // b*A + a
    const int s    = blockIdx.x >> 5;            // 0..S_D2-1
    const int b = pair >> 4;
    const int a = pair & 15;
    const int tid = threadIdx.x;
    const int im = g_imin[b];
    const int i0 = s * CH2;                      // 1024 float4 per split

    const float4* __restrict__ af = (const float4*)(auged + ((size_t)b * A + a) * D) + i0 + tid;
    const float4* __restrict__ cf = (const float4*)(queue + (size_t)im * D) + i0 + tid;

    float4 av[4], cv[4];
#pragma unroll
    for (int u = 0; u < 4; u++) av[u] = af[u * 256];
#pragma unroll
    for (int u = 0; u < 4; u++) cv[u] = cf[u * 256];

    float sacc = 0.f;
#pragma unroll
    for (int u = 0; u < 4; u++) {
        float dx = av[u].x - cv[u].x, dy = av[u].y - cv[u].y;
        float dz = av[u].z - cv[u].z, dw = av[u].w - cv[u].w;
        sacc = fmaf(dx, dx, fmaf(dy, dy, fmaf(dz, dz, fmaf(dw, dw, sacc))));
    }
    __shared__ float red[8];
    const int lane = tid & 31, warp = tid >> 5;
#pragma unroll
    for (int o = 16; o > 0; o >>= 1) sacc += __shfl_down_sync(0xFFFFFFFFu, sacc, o);
    if (lane == 0) red[warp] = sacc;
    __syncthreads();
    if (tid < 8) {
        sacc = red[tid];
#pragma unroll
        for (int o = 4; o > 0; o >>= 1) sacc += __shfl_down_sync(0xFu, sacc, o);
        if (tid == 0) g_pd2[s][b][a] = sacc;
    }
}

// ---------------- kernel 4: reduce d2 + masked top-k selection (1 warp) ----------------
__global__ void k_select(const int* __restrict__ kptr) {
    const int tid = threadIdx.x;   // 32 threads
    __shared__ float d2s[B][A];
    if (tid < B * A) {
        const int b = tid >> 4, a = tid & 15;
        float v = 0.f;
#pragma unroll
        for (int s = 0; s < S_D2; s++) v += g_pd2[s][b][a];
        d2s[b][a] = v;
    }
    __syncwarp();
    if (tid == 0) {
        int k = kptr ? kptr[0] : 5;
        if (k > 16) k = 16;
        if (k < 0)  k = 0;
        for (int b = 0; b < B; b++) {
            float cd = g_cd2[b];
            float dv[16];
            int m = 0;
#pragma unroll
            for (int a = 0; a < A; a++) {
                dv[a] = d2s[b][a];
                if (dv[a] <= cd) m++;
            }
            bool used[16] = {false};
            int cnt = 0;
            for (int j = 0; j < k; j++) {
                int best = -1; float bv = INFINITY;
                for (int a = 0; a < A; a++) {
                    if (!used[a] && dv[a] <= cd && dv[a] < bv) { bv = dv[a]; best = a; }
                }
                if (best < 0) break;
                used[best] = true;
                g_selidx[b][cnt++] = best;
            }
            g_selcnt[b] = cnt;
            g_mcnt[b]   = m;
        }
    }
}

// ---------------- kernel 5: slim gather/argmax/gate ----------------
__global__ __launch_bounds__(256) void k_final(const float* __restrict__ auged_logits,
                                               const int*   __restrict__ pseudo,
                                               float* __restrict__ out) {
    const int tid = threadIdx.x;
    const int pix = blockIdx.x * 256 + tid;   // < B*HW
    const int b = pix >> 16;
    const int p = pix & (HW - 1);

    const int cnt = g_selcnt[b];              // L2-hot tiny loads
    const int m   = g_mcnt[b];

    const int pl = pseudo[(size_t)b * HW + p];
    const bool pmask = g_pmask[pix] != 0;

    float acc[C];
#pragma unroll
    for (int c = 0; c < C; c++) acc[c] = 0.f;

    for (int j = 0; j < cnt; j++) {
        const int a = g_selidx[b][j];
        const float* __restrict__ lp = auged_logits + ((size_t)(b * A + a) * C) * HW + p;
        float l[C];
        float mx = -INFINITY;
#pragma unroll
        for (int c = 0; c < C; c++) { l[c] = lp[(size_t)c * HW]; mx = fmaxf(mx, l[c]); }
        float s = 0.f;
#pragma unroll
        for (int c = 0; c < C; c++) { l[c] = __expf(l[c] - mx); s += l[c]; }
        float inv = 1.0f / s;
#pragma unroll
        for (int c = 0; c < C; c++) acc[c] = fmaf(l[c], inv, acc[c]);
    }

    const float invc = 1.0f / (float)max(cnt, 1);

    // knn label = argmax over averaged softmax (first index on tie)
    int knn = 0; float bv = acc[0];
#pragma unroll
    for (int c = 1; c < C; c++) { if (acc[c] > bv) { bv = acc[c]; knn = c; } }

    int refined = (pmask && m > 0) ? knn : pl;
    out[pix] = (float)refined;

    // avg_soft output (coalesced per-class streams)
    float* __restrict__ oavg = out + (size_t)B * HW;
#pragma unroll
    for (int c = 0; c < C; c++)
        oavg[((size_t)b * C + c) * HW + p] = acc[c] * invc;
}

// ---------------- launch ----------------
extern "C" void kernel_launch(void* const* d_in, const int* in_sizes, int n_in,
                              void* d_out, int out_size) {
    const float* source_queue = (const float*)d_in[0];
    const float* tgt_feat     = (const float*)d_in[1];
    const float* tgt_logits   = (const float*)d_in[2];
    const float* auged_feat   = (const float*)d_in[3];
    const float* auged_logits = (const float*)d_in[4];
    const int*   pseudo_label = (const int*)d_in[5];
    const int*   kptr         = (n_in > 6) ? (const int*)d_in[6] : nullptr;
    float* out = (float*)d_out;

    k_dots_tt      <<<CONFB + NDOT + NTT, 128>>>(source_queue, tgt_feat, tgt_logits);
    k_reduce_argmin<<<1, 512>>>();
    k_d2           <<<32 * S_D2, 256>>>(auged_feat, source_queue);
    k_select       <<<1, 32>>>(kptr);
    k_final        <<<(B * HW) / 256, 256>>>(auged_logits, pseudo_label, out);
    (void)in_sizes; (void)out_size;
}

// round 9
// speedup vs baseline: 1.0472x; 1.0472x over previous
#include <cuda_runtime.h>
#include <math.h>

// Problem dims (fixed by the dataset)
#define Q   512
#define D   131072           // 512*16*16
#define D4  (D/4)            // 32768 float4
#define B   2
#define A   16
#define C   19
#define HW  65536            // 256*256
#define REFINE_CONF 0.968f

// k_dots tiling: 8 rows/block, register-held tgt
#define CH     2048          // float4 per D-chunk
#define S_DOTS (D4/CH)       // 16 D-splits
#define RPB    8             // queue rows per block
#define ROWG   (Q/RPB)       // 64 row-groups
#define NDOT   (S_DOTS*ROWG) // 1024 dot blocks
#define CONFB  512           // confidence blocks: 256 pixels each (2/thread)
#define NTT    32            // tt blocks
// k_d2 tiling
#define S_TT   16
#define CHTT   (D4/S_TT)     // 2048 float4
#define S_D2   32
#define CH2    (D4/S_D2)     // 1024 float4

// ---------------- scratch (no allocations allowed) ----------------
__device__ float g_pqq[S_DOTS][Q];        // partial ||queue_q||^2
__device__ float g_pqt[S_DOTS][Q][B];     // partial queue_q . tgt_b
__device__ float g_ptt[S_TT][B];          // partial ||tgt_b||^2
__device__ int   g_imin[B];
__device__ float g_cd2[B];                // closest distance^2
__device__ float g_pd2[S_D2][B][A];       // partial ||aug - closest||^2
__device__ unsigned char g_pmask[B * HW]; // low-confidence mask

__device__ __forceinline__ float dot4(float4 a, float4 b, float acc) {
    return fmaf(a.x, b.x, fmaf(a.y, b.y, fmaf(a.z, b.z, fmaf(a.w, b.w, acc))));
}

// ---------------- kernel 1: queue dots (first) + conf mask + tt (one grid) ----------------
__global__ __launch_bounds__(128) void k_dots_tt(const float* __restrict__ queue,
                                                 const float* __restrict__ tgt,
                                                 const float* __restrict__ tgt_logits) {
    const int bid = blockIdx.x;
    const int tid = threadIdx.x;
    const int lane = tid & 31, warp = tid >> 5;
    __shared__ float red[RPB * 3][128];           // 12 KB reduce buffer

    if (bid < NDOT) {
        // dot blocks FIRST: saturate HBM from t=0
        const int s    = bid >> 6;                // D-split (ROWG = 64)
        const int rowg = bid & 63;
        const int q0   = rowg * RPB;
        const int i0   = s * CH;
        const float4* __restrict__ qf = (const float4*)queue;
        const float4* __restrict__ tf = (const float4*)tgt;

        float acc[RPB * 3];
#pragma unroll
        for (int v = 0; v < RPB * 3; v++) acc[v] = 0.f;

        const float4* __restrict__ qbase = qf + (size_t)q0 * D4 + i0 + tid;
        const float4* __restrict__ tbase = tf + i0 + tid;

        for (int off = 0; off < CH; off += 128) {
            // 10 front-batched independent loads: 2 tgt (L2-hot) + 8 queue rows (DRAM)
            float4 t0 = tbase[off];
            float4 t1 = tbase[D4 + off];
            float4 qv[RPB];
#pragma unroll
            for (int r = 0; r < RPB; r++) qv[r] = qbase[(size_t)r * D4 + off];
#pragma unroll
            for (int r = 0; r < RPB; r++) {
                acc[r * 3 + 0] = dot4(qv[r], qv[r], acc[r * 3 + 0]);
                acc[r * 3 + 1] = dot4(qv[r], t0,    acc[r * 3 + 1]);
                acc[r * 3 + 2] = dot4(qv[r], t1,    acc[r * 3 + 2]);
            }
        }

        // single block reduction at the end
#pragma unroll
        for (int v = 0; v < RPB * 3; v++) red[v][tid] = acc[v];
        __syncthreads();
        // 4 warps x 6 values each
#pragma unroll
        for (int c = 0; c < 6; c++) {
            const int v = warp * 6 + c;           // 0..23
            float ssum = red[v][lane] + red[v][lane + 32] + red[v][lane + 64] + red[v][lane + 96];
#pragma unroll
            for (int o = 16; o > 0; o >>= 1) ssum += __shfl_down_sync(0xFFFFFFFFu, ssum, o);
            if (lane == 0) {
                const int r = v / 3, cc = v % 3;
                if (cc == 0) g_pqq[s][q0 + r]         = ssum;
                else         g_pqt[s][q0 + r][cc - 1] = ssum;
            }
        }
    } else if (bid < NDOT + CONFB) {
        // confidence blocks: 19 INDEPENDENT loads (MLP), then reduce. Tail filler.
        const int cb = bid - NDOT;
#pragma unroll
        for (int u = 0; u < 2; u++) {
            const int pix = cb * 256 + u * 128 + tid;
            const int b = pix >> 16;
            const int p = pix & (HW - 1);
            const float* __restrict__ tp = tgt_logits + (size_t)b * C * HW + p;
            float tl[C];
#pragma unroll
            for (int c = 0; c < C; c++) tl[c] = tp[(size_t)c * HW];
            float mx = tl[0];
#pragma unroll
            for (int c = 1; c < C; c++) mx = fmaxf(mx, tl[c]);
            float s = 0.f;
#pragma unroll
            for (int c = 0; c < C; c++) s += __expf(tl[c] - mx);
            g_pmask[pix] = ((1.0f / s) < REFINE_CONF) ? 1 : 0;
        }
    } else {
        // tt blocks: 32 of them, (sc, b)
        const int s2 = bid - NDOT - CONFB;
        const int b  = s2 & 1;
        const int sc = s2 >> 1;                   // 0..15
        const float4* __restrict__ tf = (const float4*)tgt + (size_t)b * D4 + sc * CHTT;
        float sum = 0.f;
        for (int i = tid; i < CHTT; i += 128) {
            float4 t = tf[i];
            sum = dot4(t, t, sum);
        }
#pragma unroll
        for (int o = 16; o > 0; o >>= 1) sum += __shfl_down_sync(0xFFFFFFFFu, sum, o);
        if (lane == 0) red[0][warp] = sum;
        __syncthreads();
        if (tid < 4) {
            sum = red[0][tid];
#pragma unroll
            for (int o = 2; o > 0; o >>= 1) sum += __shfl_down_sync(0xFu, sum, o);
            if (tid == 0) g_ptt[sc][b] = sum;
        }
    }
}

// ---------------- kernel 2: reduce partials + argmin (stable, first idx on tie) ----------------
__global__ __launch_bounds__(512) void k_reduce_argmin() {
    const int tid = threadIdx.x;   // == q, Q == 512
    float qq = 0.f, qt0 = 0.f, qt1 = 0.f;
#pragma unroll
    for (int s = 0; s < S_DOTS; s++) {
        qq  += g_pqq[s][tid];
        qt0 += g_pqt[s][tid][0];
        qt1 += g_pqt[s][tid][1];
    }
    __shared__ float tts[B];
    if (tid < B) {
        float t = 0.f;
#pragma unroll
        for (int s = 0; s < S_TT; s++) t += g_ptt[s][tid];
        tts[tid] = t;
    }
    __shared__ float sval[512];
    __shared__ int   sidx[512];
    __syncthreads();
    for (int b = 0; b < B; b++) {
        float qt = (b == 0) ? qt0 : qt1;
        float v = qq - 2.0f * qt + tts[b];
        sval[tid] = v; sidx[tid] = tid;
        __syncthreads();
        for (int s = 256; s > 0; s >>= 1) {
            if (tid < s) {
                float ov = sval[tid + s]; int oi = sidx[tid + s];
                if (ov < sval[tid] || (ov == sval[tid] && oi < sidx[tid])) {
                    sval[tid] = ov; sidx[tid] = oi;
                }
            }
            __syncthreads();
        }
        if (tid == 0) { g_imin[b] = sidx[0]; g_cd2[b] = sval[0]; }
        __syncthreads();
    }
}

// ---------------- kernel 3: ||aug[b,a] - closest_b||^2, one pass, MLP 8 ----------------
__global__ __launch_bounds__(256) void k_d2(const float* __restrict__ auged,
                                            const float* __restrict__ queue) {
    const int pair = blockIdx.x & 31;            // b*A + a
    const int s    = blockIdx.x >> 5;            // 0..S_D2-1
    const int b = pair >> 4;
    const int a = pair & 15;
    const int tid = threadIdx.x;
    const int im = g_imin[b];
    const int i0 = s * CH2;                      // 1024 float4 per split

    const float4* __restrict__ af = (const float4*)(auged + ((size_t)b * A + a) * D) + i0 + tid;
    const float4* __restrict__ cf = (const float4*)(queue + (size_t)im * D) + i0 + tid;

    float4 av[4], cv[4];
#pragma unroll
    for (int u = 0; u < 4; u++) av[u] = af[u * 256];
#pragma unroll
    for (int u = 0; u < 4; u++) cv[u] = cf[u * 256];

    float sacc = 0.f;
#pragma unroll
    for (int u = 0; u < 4; u++) {
        float dx = av[u].x - cv[u].x, dy = av[u].y - cv[u].y;
        float dz = av[u].z - cv[u].z, dw = av[u].w - cv[u].w;
        sacc = fmaf(dx, dx, fmaf(dy, dy, fmaf(dz, dz, fmaf(dw, dw, sacc))));
    }
    __shared__ float red[8];
    const int lane = tid & 31, warp = tid >> 5;
#pragma unroll
    for (int o = 16; o > 0; o >>= 1) sacc += __shfl_down_sync(0xFFFFFFFFu, sacc, o);
    if (lane == 0) red[warp] = sacc;
    __syncthreads();
    if (tid < 8) {
        sacc = red[tid];
#pragma unroll
        for (int o = 4; o > 0; o >>= 1) sacc += __shfl_down_sync(0xFu, sacc, o);
        if (tid == 0) g_pd2[s][b][a] = sacc;
    }
}

// ---------------- kernel 4: parallel select preamble + gather/argmax/gate ----------------
__global__ __launch_bounds__(256) void k_final(const float* __restrict__ auged_logits,
                                               const int*   __restrict__ pseudo,
                                               const int*   __restrict__ kptr,
                                               float* __restrict__ out) {
    __shared__ float d2s[B][A];
    __shared__ int   ssel[B][16];
    __shared__ int   scnt[B];
    __shared__ int   smc[B];
    const int tid = threadIdx.x;

    const int pix = blockIdx.x * 256 + tid;   // < B*HW
    const int b = pix >> 16;
    const int p = pix & (HW - 1);

    // issue independent loads before the preamble barrier
    const int  pl    = pseudo[(size_t)b * HW + p];
    const bool pmask = g_pmask[pix] != 0;

    // parallel d2 reduce: 8 threads per (b,a) pair, 4 loads each + width-8 shuffle
    {
        const int pairid = tid >> 3;          // 0..31
        const int sub    = tid & 7;
        const int bb = pairid >> 4, aa = pairid & 15;
        float v = 0.f;
#pragma unroll
        for (int s = 0; s < 4; s++) v += g_pd2[sub + s * 8][bb][aa];
#pragma unroll
        for (int o = 4; o > 0; o >>= 1) v += __shfl_down_sync(0xFFFFFFFFu, v, o, 8);
        if (sub == 0) d2s[bb][aa] = v;
    }
    __syncthreads();
    if (tid == 0) {
        int k = kptr ? kptr[0] : 5;
        if (k > 16) k = 16;
        if (k < 0)  k = 0;
        for (int bb = 0; bb < B; bb++) {
            float cd = g_cd2[bb];
            float dv[16];
            int m = 0;
#pragma unroll
            for (int a = 0; a < A; a++) {
                dv[a] = d2s[bb][a];
                if (dv[a] <= cd) m++;
            }
            bool used[16] = {false};
            int cnt = 0;
            for (int j = 0; j < k; j++) {
                int best = -1; float bv = INFINITY;
                for (int a = 0; a < A; a++) {
                    if (!used[a] && dv[a] <= cd && dv[a] < bv) { bv = dv[a]; best = a; }
                }
                if (best < 0) break;
                used[best] = true;
                ssel[bb][cnt++] = best;
            }
            scnt[bb] = cnt;
            smc[bb]  = m;
        }
    }
    __syncthreads();

    const int cnt = scnt[b];
    const int m   = smc[b];

    float acc[C];
#pragma unroll
    for (int c = 0; c < C; c++) acc[c] = 0.f;

    for (int j = 0; j < cnt; j++) {
        const int a = ssel[b][j];
        const float* __restrict__ lp = auged_logits + ((size_t)(b * A + a) * C) * HW + p;
        float l[C];
        float mx = -INFINITY;
#pragma unroll
        for (int c = 0; c < C; c++) { l[c] = lp[(size_t)c * HW]; mx = fmaxf(mx, l[c]); }
        float s = 0.f;
#pragma unroll
        for (int c = 0; c < C; c++) { l[c] = __expf(l[c] - mx); s += l[c]; }
        float inv = 1.0f / s;
#pragma unroll
        for (int c = 0; c < C; c++) acc[c] = fmaf(l[c], inv, acc[c]);
    }

    const float invc = 1.0f / (float)max(cnt, 1);

    // knn label = argmax over averaged softmax (first index on tie)
    int knn = 0; float bv = acc[0];
#pragma unroll
    for (int c = 1; c < C; c++) { if (acc[c] > bv) { bv = acc[c]; knn = c; } }

    int refined = (pmask && m > 0) ? knn : pl;
    out[pix] = (float)refined;

    // avg_soft output (coalesced per-class streams)
    float* __restrict__ oavg = out + (size_t)B * HW;
#pragma unroll
    for (int c = 0; c < C; c++)
        oavg[((size_t)b * C + c) * HW + p] = acc[c] * invc;
}

// ---------------- launch ----------------
extern "C" void kernel_launch(void* const* d_in, const int* in_sizes, int n_in,
                              void* d_out, int out_size) {
    const float* source_queue = (const float*)d_in[0];
    const float* tgt_feat     = (const float*)d_in[1];
    const float* tgt_logits   = (const float*)d_in[2];
    const float* auged_feat   = (const float*)d_in[3];
    const float* auged_logits = (const float*)d_in[4];
    const int*   pseudo_label = (const int*)d_in[5];
    const int*   kptr         = (n_in > 6) ? (const int*)d_in[6] : nullptr;
    float* out = (float*)d_out;

    k_dots_tt      <<<NDOT + CONFB + NTT, 128>>>(source_queue, tgt_feat, tgt_logits);
    k_reduce_argmin<<<1, 512>>>();
    k_d2           <<<32 * S_D2, 256>>>(auged_feat, source_queue);
    k_final        <<<(B * HW) / 256, 256>>>(auged_logits, pseudo_label, kptr, out);
    (void)in_sizes; (void)out_size;
}